// round 1
// baseline (speedup 1.0000x reference)
#include <cuda_runtime.h>

#define NPTS 262144
#define WW   128
#define TM   64
#define HS   132
#define NTH  256

// ---- scratch (__device__ globals: no allocation allowed) ----
__device__ float g_feats[NPTS * 8];   // [r, ux, uy, uz, 1/(1+r), a, 0, 0]
__device__ float g_ic[NPTS];
__device__ float g_dp[NPTS * 3];

// node+1 for GL nodes {-sqrt(3/5), 0, +sqrt(3/5)}
__constant__ float c_np1[3] = {1.0f - 0.77459669f, 1.0f, 1.0f + 0.77459669f};

// ---- packed f32x2 helpers (2x fp32 FMA throughput on sm_103a) ----
__device__ __forceinline__ unsigned long long pack2(float x) {
    unsigned int u = __float_as_uint(x);
    unsigned long long r;
    asm("mov.b64 %0, {%1, %2};" : "=l"(r) : "r"(u), "r"(u));
    return r;
}
__device__ __forceinline__ void fma2(unsigned long long& d,
                                     unsigned long long a,
                                     unsigned long long b) {
    asm("fma.rn.f32x2 %0, %1, %2, %0;" : "+l"(d) : "l"(a), "l"(b));
}
__device__ __forceinline__ float2 unpack2(unsigned long long v) {
    unsigned int lo, hi;
    asm("mov.b64 {%0, %1}, %2;" : "=r"(lo), "=r"(hi) : "l"(v));
    return make_float2(__uint_as_float(lo), __uint_as_float(hi));
}

// ---- kernel 1: per-point features ----
__global__ void prep_kernel(const float4* __restrict__ tx) {
    int i = blockIdx.x * blockDim.x + threadIdx.x;
    if (i >= NPTS) return;
    float4 v = tx[i];
    float tf = v.x, x = v.y, y = v.z, z = v.w;
    float r = sqrtf(x * x + y * y + z * z);
    float rs = fmaxf(r, 1e-8f);
    float inv = 1.0f / (1.0f + r);
    float a = tf * 0.5f;               // T0 = 0
    float* o = g_feats + i * 8;
    // CLIP = 1.0 -> min(r, max(r)) == r : no global reduction needed
    ((float4*)o)[0] = make_float4(r, x / rs, y / rs, z / rs);
    ((float4*)o)[1] = make_float4(inv, a, 0.f, 0.f);
}

// ---- kernel 2/3: fused MLP (tiled GEMM in SMEM, f32x2 microkernel) ----
template <int DIN, bool ISDP>
__global__ void __launch_bounds__(NTH, 1) mlp_kernel(
    const float* __restrict__ Win, const float* __restrict__ bin,
    const float* __restrict__ Wh,  const float* __restrict__ bh,
    const float* __restrict__ Wout, const float* __restrict__ bout) {
    extern __shared__ float sm[];
    float* Ws = sm;                 // 128*128
    float* Bs = Ws + WW * WW;       // 128
    float* Xs = Bs + WW;            // 64*8
    float* H0 = Xs + TM * 8;        // 64*132
    float* H1 = H0 + TM * HS;       // 64*132

    const int tid = threadIdx.x;
    const int base = blockIdx.x * TM;
    const int tx = tid & 15, ty = tid >> 4;
    const int m0 = ty * 4, jb = tx * 8;

    // load first-layer inputs for this tile
    if (tid < TM) {
        float* x = Xs + tid * 8;
        if (ISDP) {
            int g = base + tid;
            int p = g / 3;
            int nd = g - 3 * p;
            const float* f = g_feats + p * 8;
            float a = f[5];
            x[0] = a * c_np1[nd];
            x[1] = f[0]; x[2] = f[1]; x[3] = f[2]; x[4] = f[3];
            x[5] = f[4]; x[6] = 0.f; x[7] = 0.f;
        } else {
            int p = base + tid;
            const float* f = g_feats + p * 8;
            x[0] = f[0]; x[1] = f[1]; x[2] = f[2]; x[3] = f[3];
            x[4] = f[4]; x[5] = 0.f; x[6] = 0.f; x[7] = 0.f;
        }
    }
    for (int i = tid; i < DIN * (WW / 4); i += NTH)
        ((float4*)Ws)[i] = ((const float4*)Win)[i];
    if (tid < WW / 4) ((float4*)Bs)[tid] = ((const float4*)bin)[tid];
    __syncthreads();

    unsigned long long acc[4][4];

    // ---- input layer: Xs [64,DIN] @ Win [DIN,128] ----
    {
        ulonglong2 b01 = *(const ulonglong2*)(Bs + jb);
        ulonglong2 b23 = *(const ulonglong2*)(Bs + jb + 4);
#pragma unroll
        for (int mm = 0; mm < 4; mm++) {
            acc[mm][0] = b01.x; acc[mm][1] = b01.y;
            acc[mm][2] = b23.x; acc[mm][3] = b23.y;
        }
#pragma unroll
        for (int k = 0; k < DIN; k++) {
            ulonglong2 w01 = *(const ulonglong2*)(Ws + k * WW + jb);
            ulonglong2 w23 = *(const ulonglong2*)(Ws + k * WW + jb + 4);
#pragma unroll
            for (int mm = 0; mm < 4; mm++) {
                unsigned long long hb = pack2(Xs[(m0 + mm) * 8 + k]);
                fma2(acc[mm][0], hb, w01.x);
                fma2(acc[mm][1], hb, w01.y);
                fma2(acc[mm][2], hb, w23.x);
                fma2(acc[mm][3], hb, w23.y);
            }
        }
#pragma unroll
        for (int mm = 0; mm < 4; mm++)
#pragma unroll
            for (int jp = 0; jp < 4; jp++) {
                float2 v = unpack2(acc[mm][jp]);
                v.x = tanhf(v.x); v.y = tanhf(v.y);
                *(float2*)(H0 + (m0 + mm) * HS + jb + jp * 2) = v;
            }
    }

    // ---- 3 hidden layers: H [64,128] @ Wh[l] [128,128] ----
    float* cur = H0;
    float* nxt = H1;
    for (int l = 0; l < 3; l++) {
        __syncthreads();
        const float4* wsrc = (const float4*)(Wh + l * WW * WW);
        for (int i = tid; i < WW * WW / 4; i += NTH)
            ((float4*)Ws)[i] = wsrc[i];
        if (tid < WW / 4)
            ((float4*)Bs)[tid] = ((const float4*)(bh + l * WW))[tid];
        __syncthreads();

        ulonglong2 b01 = *(const ulonglong2*)(Bs + jb);
        ulonglong2 b23 = *(const ulonglong2*)(Bs + jb + 4);
#pragma unroll
        for (int mm = 0; mm < 4; mm++) {
            acc[mm][0] = b01.x; acc[mm][1] = b01.y;
            acc[mm][2] = b23.x; acc[mm][3] = b23.y;
        }

#pragma unroll 4
        for (int k = 0; k < WW; k += 4) {
            float4 ha[4];
#pragma unroll
            for (int mm = 0; mm < 4; mm++)
                ha[mm] = *(const float4*)(cur + (m0 + mm) * HS + k);
#pragma unroll
            for (int kk = 0; kk < 4; kk++) {
                ulonglong2 w01 = *(const ulonglong2*)(Ws + (k + kk) * WW + jb);
                ulonglong2 w23 = *(const ulonglong2*)(Ws + (k + kk) * WW + jb + 4);
#pragma unroll
                for (int mm = 0; mm < 4; mm++) {
                    float hv = (kk == 0) ? ha[mm].x
                             : (kk == 1) ? ha[mm].y
                             : (kk == 2) ? ha[mm].z : ha[mm].w;
                    unsigned long long hb = pack2(hv);
                    fma2(acc[mm][0], hb, w01.x);
                    fma2(acc[mm][1], hb, w01.y);
                    fma2(acc[mm][2], hb, w23.x);
                    fma2(acc[mm][3], hb, w23.y);
                }
            }
        }
#pragma unroll
        for (int mm = 0; mm < 4; mm++)
#pragma unroll
            for (int jp = 0; jp < 4; jp++) {
                float2 v = unpack2(acc[mm][jp]);
                v.x = tanhf(v.x); v.y = tanhf(v.y);
                *(float2*)(nxt + (m0 + mm) * HS + jb + jp * 2) = v;
            }
        float* t = cur; cur = nxt; nxt = t;
    }
    __syncthreads();

    // ---- output layer: H [64,128] @ Wout [128,1] ----
    if (tid < WW / 4) ((float4*)Xs)[tid] = ((const float4*)Wout)[tid];
    __syncthreads();
    {
        int row = tid >> 2, part = tid & 3;
        const float* h = cur + row * HS + part * 32;
        const float* w = Xs + part * 32;
        float s = 0.f;
#pragma unroll
        for (int k = 0; k < 32; k++) s = fmaf(h[k], w[k], s);
        s += __shfl_xor_sync(0xffffffffu, s, 1);
        s += __shfl_xor_sync(0xffffffffu, s, 2);
        if (part == 0) {
            float o = s + bout[0];
            if (ISDP) g_dp[base + row] = o;
            else      g_ic[base + row] = o;
        }
    }
}

// ---- kernel 4: GL quadrature + final scaling ----
__global__ void combine_kernel(float* __restrict__ out) {
    int i = blockIdx.x * blockDim.x + threadIdx.x;
    if (i >= NPTS) return;
    const float* f = g_feats + i * 8;
    float a = f[5], inv = f[4];
    const float w0 = (float)(5.0 / 9.0), w1 = (float)(8.0 / 9.0);
    float s = w0 * g_dp[3 * i] + w1 * g_dp[3 * i + 1] + w0 * g_dp[3 * i + 2];
    out[i] = (g_ic[i] + a * s) * inv;
}

extern "C" void kernel_launch(void* const* d_in, const int* in_sizes, int n_in,
                              void* d_out, int out_size) {
    const float* tx      = (const float*)d_in[0];
    const float* dp_Win  = (const float*)d_in[1];
    const float* dp_bin  = (const float*)d_in[2];
    const float* dp_Wh   = (const float*)d_in[3];
    const float* dp_bh   = (const float*)d_in[4];
    const float* dp_Wout = (const float*)d_in[5];
    const float* dp_bout = (const float*)d_in[6];
    const float* ic_Win  = (const float*)d_in[7];
    const float* ic_bin  = (const float*)d_in[8];
    const float* ic_Wh   = (const float*)d_in[9];
    const float* ic_bh   = (const float*)d_in[10];
    const float* ic_Wout = (const float*)d_in[11];
    const float* ic_bout = (const float*)d_in[12];
    float* out = (float*)d_out;

    const int smem = (WW * WW + WW + TM * 8 + 2 * TM * HS) * (int)sizeof(float);
    cudaFuncSetAttribute(mlp_kernel<5, false>,
                         cudaFuncAttributeMaxDynamicSharedMemorySize, smem);
    cudaFuncSetAttribute(mlp_kernel<6, true>,
                         cudaFuncAttributeMaxDynamicSharedMemorySize, smem);

    prep_kernel<<<NPTS / 256, 256>>>((const float4*)tx);
    mlp_kernel<5, false><<<NPTS / TM, NTH, smem>>>(
        ic_Win, ic_bin, ic_Wh, ic_bh, ic_Wout, ic_bout);
    mlp_kernel<6, true><<<3 * NPTS / TM, NTH, smem>>>(
        dp_Win, dp_bin, dp_Wh, dp_bh, dp_Wout, dp_bout);
    combine_kernel<<<NPTS / 256, 256>>>(out);
}

// round 2
// speedup vs baseline: 1.0007x; 1.0007x over previous
#include <cuda_runtime.h>

#define NPTS 262144
#define WW   128
#define TM   64
#define HS   132
#define NTH  256

// ---- scratch (__device__ globals: no allocation allowed) ----
__device__ float g_feats[NPTS * 8];   // [r, ux, uy, uz, 1/(1+r), a, 0, 0]
__device__ float g_ic[NPTS];
__device__ float g_dp[NPTS * 3];

// node+1 for GL nodes {-sqrt(3/5), 0, +sqrt(3/5)}
__constant__ float c_np1[3] = {1.0f - 0.77459669f, 1.0f, 1.0f + 0.77459669f};

// ---- packed f32x2 helpers (2x fp32 FMA throughput on sm_103a) ----
__device__ __forceinline__ unsigned long long pack2(float x) {
    unsigned int u = __float_as_uint(x);
    unsigned long long r;
    asm("mov.b64 %0, {%1, %2};" : "=l"(r) : "r"(u), "r"(u));
    return r;
}
__device__ __forceinline__ void fma2(unsigned long long& d,
                                     unsigned long long a,
                                     unsigned long long b) {
    asm("fma.rn.f32x2 %0, %1, %2, %0;" : "+l"(d) : "l"(a), "l"(b));
}
__device__ __forceinline__ float2 unpack2(unsigned long long v) {
    unsigned int lo, hi;
    asm("mov.b64 {%0, %1}, %2;" : "=r"(lo), "=r"(hi) : "l"(v));
    return make_float2(__uint_as_float(lo), __uint_as_float(hi));
}

// ---- kernel 1: per-point features ----
__global__ void prep_kernel(const float4* __restrict__ tx) {
    int i = blockIdx.x * blockDim.x + threadIdx.x;
    if (i >= NPTS) return;
    float4 v = tx[i];
    float tf = v.x, x = v.y, y = v.z, z = v.w;
    float r = sqrtf(x * x + y * y + z * z);
    float rs = fmaxf(r, 1e-8f);
    float inv = 1.0f / (1.0f + r);
    float a = tf * 0.5f;               // T0 = 0
    float* o = g_feats + i * 8;
    // CLIP = 1.0 -> min(r, max(r)) == r : no global reduction needed
    ((float4*)o)[0] = make_float4(r, x / rs, y / rs, z / rs);
    ((float4*)o)[1] = make_float4(inv, a, 0.f, 0.f);
}

// ---- kernel 2/3: fused MLP (tiled GEMM in SMEM, f32x2 microkernel) ----
template <int DIN, bool ISDP>
__global__ void __launch_bounds__(NTH, 1) mlp_kernel(
    const float* __restrict__ Win, const float* __restrict__ bin,
    const float* __restrict__ Wh,  const float* __restrict__ bh,
    const float* __restrict__ Wout, const float* __restrict__ bout) {
    extern __shared__ float sm[];
    float* Ws = sm;                 // 128*128
    float* Bs = Ws + WW * WW;       // 128
    float* Xs = Bs + WW;            // 64*8
    float* H0 = Xs + TM * 8;        // 64*132
    float* H1 = H0 + TM * HS;       // 64*132

    const int tid = threadIdx.x;
    const int base = blockIdx.x * TM;
    const int tx = tid & 15, ty = tid >> 4;
    const int m0 = ty * 4, jb = tx * 8;

    // load first-layer inputs for this tile
    if (tid < TM) {
        float* x = Xs + tid * 8;
        if (ISDP) {
            int g = base + tid;
            int p = g / 3;
            int nd = g - 3 * p;
            const float* f = g_feats + p * 8;
            float a = f[5];
            x[0] = a * c_np1[nd];
            x[1] = f[0]; x[2] = f[1]; x[3] = f[2]; x[4] = f[3];
            x[5] = f[4]; x[6] = 0.f; x[7] = 0.f;
        } else {
            int p = base + tid;
            const float* f = g_feats + p * 8;
            x[0] = f[0]; x[1] = f[1]; x[2] = f[2]; x[3] = f[3];
            x[4] = f[4]; x[5] = 0.f; x[6] = 0.f; x[7] = 0.f;
        }
    }
    for (int i = tid; i < DIN * (WW / 4); i += NTH)
        ((float4*)Ws)[i] = ((const float4*)Win)[i];
    if (tid < WW / 4) ((float4*)Bs)[tid] = ((const float4*)bin)[tid];
    __syncthreads();

    unsigned long long acc[4][4];

    // ---- input layer: Xs [64,DIN] @ Win [DIN,128] ----
    {
        ulonglong2 b01 = *(const ulonglong2*)(Bs + jb);
        ulonglong2 b23 = *(const ulonglong2*)(Bs + jb + 4);
#pragma unroll
        for (int mm = 0; mm < 4; mm++) {
            acc[mm][0] = b01.x; acc[mm][1] = b01.y;
            acc[mm][2] = b23.x; acc[mm][3] = b23.y;
        }
#pragma unroll
        for (int k = 0; k < DIN; k++) {
            ulonglong2 w01 = *(const ulonglong2*)(Ws + k * WW + jb);
            ulonglong2 w23 = *(const ulonglong2*)(Ws + k * WW + jb + 4);
#pragma unroll
            for (int mm = 0; mm < 4; mm++) {
                unsigned long long hb = pack2(Xs[(m0 + mm) * 8 + k]);
                fma2(acc[mm][0], hb, w01.x);
                fma2(acc[mm][1], hb, w01.y);
                fma2(acc[mm][2], hb, w23.x);
                fma2(acc[mm][3], hb, w23.y);
            }
        }
#pragma unroll
        for (int mm = 0; mm < 4; mm++)
#pragma unroll
            for (int jp = 0; jp < 4; jp++) {
                float2 v = unpack2(acc[mm][jp]);
                v.x = tanhf(v.x); v.y = tanhf(v.y);
                *(float2*)(H0 + (m0 + mm) * HS + jb + jp * 2) = v;
            }
    }

    // ---- 3 hidden layers: H [64,128] @ Wh[l] [128,128] ----
    float* cur = H0;
    float* nxt = H1;
    for (int l = 0; l < 3; l++) {
        __syncthreads();
        const float4* wsrc = (const float4*)(Wh + l * WW * WW);
        for (int i = tid; i < WW * WW / 4; i += NTH)
            ((float4*)Ws)[i] = wsrc[i];
        if (tid < WW / 4)
            ((float4*)Bs)[tid] = ((const float4*)(bh + l * WW))[tid];
        __syncthreads();

        ulonglong2 b01 = *(const ulonglong2*)(Bs + jb);
        ulonglong2 b23 = *(const ulonglong2*)(Bs + jb + 4);
#pragma unroll
        for (int mm = 0; mm < 4; mm++) {
            acc[mm][0] = b01.x; acc[mm][1] = b01.y;
            acc[mm][2] = b23.x; acc[mm][3] = b23.y;
        }

#pragma unroll 4
        for (int k = 0; k < WW; k += 4) {
            float4 ha[4];
#pragma unroll
            for (int mm = 0; mm < 4; mm++)
                ha[mm] = *(const float4*)(cur + (m0 + mm) * HS + k);
#pragma unroll
            for (int kk = 0; kk < 4; kk++) {
                ulonglong2 w01 = *(const ulonglong2*)(Ws + (k + kk) * WW + jb);
                ulonglong2 w23 = *(const ulonglong2*)(Ws + (k + kk) * WW + jb + 4);
#pragma unroll
                for (int mm = 0; mm < 4; mm++) {
                    float hv = (kk == 0) ? ha[mm].x
                             : (kk == 1) ? ha[mm].y
                             : (kk == 2) ? ha[mm].z : ha[mm].w;
                    unsigned long long hb = pack2(hv);
                    fma2(acc[mm][0], hb, w01.x);
                    fma2(acc[mm][1], hb, w01.y);
                    fma2(acc[mm][2], hb, w23.x);
                    fma2(acc[mm][3], hb, w23.y);
                }
            }
        }
#pragma unroll
        for (int mm = 0; mm < 4; mm++)
#pragma unroll
            for (int jp = 0; jp < 4; jp++) {
                float2 v = unpack2(acc[mm][jp]);
                v.x = tanhf(v.x); v.y = tanhf(v.y);
                *(float2*)(nxt + (m0 + mm) * HS + jb + jp * 2) = v;
            }
        float* t = cur; cur = nxt; nxt = t;
    }
    __syncthreads();

    // ---- output layer: H [64,128] @ Wout [128,1] ----
    if (tid < WW / 4) ((float4*)Xs)[tid] = ((const float4*)Wout)[tid];
    __syncthreads();
    {
        int row = tid >> 2, part = tid & 3;
        const float* h = cur + row * HS + part * 32;
        const float* w = Xs + part * 32;
        float s = 0.f;
#pragma unroll
        for (int k = 0; k < 32; k++) s = fmaf(h[k], w[k], s);
        s += __shfl_xor_sync(0xffffffffu, s, 1);
        s += __shfl_xor_sync(0xffffffffu, s, 2);
        if (part == 0) {
            float o = s + bout[0];
            if (ISDP) g_dp[base + row] = o;
            else      g_ic[base + row] = o;
        }
    }
}

// ---- kernel 4: GL quadrature + final scaling ----
__global__ void combine_kernel(float* __restrict__ out) {
    int i = blockIdx.x * blockDim.x + threadIdx.x;
    if (i >= NPTS) return;
    const float* f = g_feats + i * 8;
    float a = f[5], inv = f[4];
    const float w0 = (float)(5.0 / 9.0), w1 = (float)(8.0 / 9.0);
    float s = w0 * g_dp[3 * i] + w1 * g_dp[3 * i + 1] + w0 * g_dp[3 * i + 2];
    out[i] = (g_ic[i] + a * s) * inv;
}

extern "C" void kernel_launch(void* const* d_in, const int* in_sizes, int n_in,
                              void* d_out, int out_size) {
    const float* tx      = (const float*)d_in[0];
    const float* dp_Win  = (const float*)d_in[1];
    const float* dp_bin  = (const float*)d_in[2];
    const float* dp_Wh   = (const float*)d_in[3];
    const float* dp_bh   = (const float*)d_in[4];
    const float* dp_Wout = (const float*)d_in[5];
    const float* dp_bout = (const float*)d_in[6];
    const float* ic_Win  = (const float*)d_in[7];
    const float* ic_bin  = (const float*)d_in[8];
    const float* ic_Wh   = (const float*)d_in[9];
    const float* ic_bh   = (const float*)d_in[10];
    const float* ic_Wout = (const float*)d_in[11];
    const float* ic_bout = (const float*)d_in[12];
    float* out = (float*)d_out;

    const int smem = (WW * WW + WW + TM * 8 + 2 * TM * HS) * (int)sizeof(float);
    cudaFuncSetAttribute(mlp_kernel<5, false>,
                         cudaFuncAttributeMaxDynamicSharedMemorySize, smem);
    cudaFuncSetAttribute(mlp_kernel<6, true>,
                         cudaFuncAttributeMaxDynamicSharedMemorySize, smem);

    prep_kernel<<<NPTS / 256, 256>>>((const float4*)tx);
    mlp_kernel<5, false><<<NPTS / TM, NTH, smem>>>(
        ic_Win, ic_bin, ic_Wh, ic_bh, ic_Wout, ic_bout);
    mlp_kernel<6, true><<<3 * NPTS / TM, NTH, smem>>>(
        dp_Win, dp_bin, dp_Wh, dp_bh, dp_Wout, dp_bout);
    combine_kernel<<<NPTS / 256, 256>>>(out);
}

// round 4
// speedup vs baseline: 4.3805x; 4.3772x over previous
#include <cuda_runtime.h>
#include <cuda_bf16.h>
#include <cstdint>

#define NPTS 262144

// ---------------- scratch (__device__ globals; no allocation allowed) -----
__device__ float g_feats[NPTS * 8];   // [r, ux, uy, uz, inv, a, 0, 0]
__device__ float g_ic[NPTS];
__device__ float g_dp[NPTS * 3];

// Pre-packed B fragments for mma.m16n8k16 (per-lane uint2 = {b0,b1}).
// Per MLP: 25 "ksteps" (1 input + 3 layers * 8) x 16 nfrags x 32 lanes.
#define FRAGS_PER_MLP (25 * 16 * 32)   // 12800 uint2
__device__ uint2 g_WpH[2 * FRAGS_PER_MLP];
__device__ uint2 g_WpL[2 * FRAGS_PER_MLP];

__constant__ float c_np1[3] = {1.0f - 0.7745966692f, 1.0f, 1.0f + 0.7745966692f};

// ---------------- math helpers --------------------------------------------
__device__ __forceinline__ float fast_tanh(float x) {
    // tanh(x) = 1 - 2/(exp(2x)+1)
    float e, r;
    asm("ex2.approx.f32 %0, %1;" : "=f"(e) : "f"(x * 2.8853900817779268f));
    asm("rcp.approx.f32 %0, %1;" : "=f"(r) : "f"(e + 1.0f));
    return fmaf(-2.0f, r, 1.0f);
}
// pack (v0 -> low bf16, v1 -> high bf16); uh = hi parts, ul = residual lo parts
__device__ __forceinline__ void split2(float v0, float v1, uint32_t& uh, uint32_t& ul) {
    uint32_t u;
    asm("cvt.rn.bf16x2.f32 %0, %1, %2;" : "=r"(u) : "f"(v1), "f"(v0));
    float b0 = __uint_as_float(u << 16);
    float b1 = __uint_as_float(u & 0xffff0000u);
    uh = u;
    asm("cvt.rn.bf16x2.f32 %0, %1, %2;" : "=r"(ul) : "f"(v1 - b1), "f"(v0 - b0));
}

// bf16 HMMA: D = A(16x16) * B(16x8) + D, fp32 accum
__device__ __forceinline__ void mma16816(float c[4], uint32_t a0, uint32_t a1,
                                         uint32_t a2, uint32_t a3,
                                         uint32_t b0, uint32_t b1) {
    asm volatile(
        "mma.sync.aligned.m16n8k16.row.col.f32.bf16.bf16.f32 "
        "{%0,%1,%2,%3}, {%4,%5,%6,%7}, {%8,%9}, {%0,%1,%2,%3};"
        : "+f"(c[0]), "+f"(c[1]), "+f"(c[2]), "+f"(c[3])
        : "r"(a0), "r"(a1), "r"(a2), "r"(a3), "r"(b0), "r"(b1));
}

// ---------------- kernel 1: per-point features ----------------------------
__global__ void prep_kernel(const float4* __restrict__ tx) {
    int i = blockIdx.x * blockDim.x + threadIdx.x;
    if (i >= NPTS) return;
    float4 v = tx[i];
    float r = sqrtf(v.y * v.y + v.z * v.z + v.w * v.w);
    float rs = fmaxf(r, 1e-8f);
    float inv = 1.0f / (1.0f + r);
    float a = v.x * 0.5f;   // T0 = 0; CLIP = 1 -> min(r, max r) == r
    float* o = g_feats + i * 8;
    ((float4*)o)[0] = make_float4(r, v.y / rs, v.z / rs, v.w / rs);
    ((float4*)o)[1] = make_float4(inv, a, 0.f, 0.f);
}

// ---------------- kernel 2: pack weights into B-fragment layout ------------
// B frag (k16n8, col-major): b0 = (k = kb+2q, kb+2q+1; n = 8j + lane/4),
//                            b1 = (k = kb+8+2q, kb+8+2q+1; same n)
__global__ void wprep_kernel(const float* __restrict__ dp_Win,
                             const float* __restrict__ dp_Wh,
                             const float* __restrict__ ic_Win,
                             const float* __restrict__ ic_Wh) {
    int t = blockIdx.x * blockDim.x + threadIdx.x;
    if (t >= 2 * FRAGS_PER_MLP) return;
    int lane = t & 31;
    int g = t >> 5;                // 0..799
    int m = g / 400;               // 0 = dp, 1 = ic
    int gg = g - m * 400;
    int ks = gg >> 4;              // 0 = input layer, 1..24 = hidden
    int j = gg & 15;
    const float* Win = m ? ic_Win : dp_Win;
    const float* Wh  = m ? ic_Wh  : dp_Wh;
    int din = m ? 5 : 6;
    int q = lane & 3;
    int n = j * 8 + (lane >> 2);
    float w00, w01, w10, w11;
    if (ks == 0) {
        int k0 = 2 * q;
        w00 = (k0     < din) ? Win[k0 * 128 + n]       : 0.f;
        w01 = (k0 + 1 < din) ? Win[(k0 + 1) * 128 + n] : 0.f;
        w10 = 0.f; w11 = 0.f;      // k >= 8 is always padding
    } else {
        int l = (ks - 1) >> 3, s = (ks - 1) & 7;
        int kb = 16 * s + 2 * q;
        const float* W = Wh + l * 16384;
        w00 = W[kb * 128 + n];       w01 = W[(kb + 1) * 128 + n];
        w10 = W[(kb + 8) * 128 + n]; w11 = W[(kb + 9) * 128 + n];
    }
    uint32_t h0, l0, h1, l1;
    split2(w00, w01, h0, l0);
    split2(w10, w11, h1, l1);
    g_WpH[t] = make_uint2(h0, h1);
    g_WpL[t] = make_uint2(l0, l1);
}

// ---------------- input A-fragment builder --------------------------------
template <bool ISDP>
__device__ __forceinline__ void build_in(int grow, int q, uint32_t& ah, uint32_t& al) {
    float xa, xb;
    if (ISDP) {
        int p = grow / 3, nd = grow - 3 * p;
        float4 f0 = *(const float4*)(g_feats + p * 8);       // r ux uy uz
        float2 f1 = *(const float2*)(g_feats + p * 8 + 4);   // inv a
        float tt = f1.y * c_np1[nd];
        // x = [t, r, ux, uy, uz, inv, 0, ...]
        xa = (q == 0) ? tt   : (q == 1) ? f0.y : (q == 2) ? f0.w : 0.f;
        xb = (q == 0) ? f0.x : (q == 1) ? f0.z : (q == 2) ? f1.x : 0.f;
    } else {
        float4 f0 = *(const float4*)(g_feats + grow * 8);
        float2 f1 = *(const float2*)(g_feats + grow * 8 + 4);
        // x = [r, ux, uy, uz, inv, 0, ...]
        xa = (q == 0) ? f0.x : (q == 1) ? f0.z : (q == 2) ? f1.x : 0.f;
        xb = (q == 0) ? f0.y : (q == 1) ? f0.w : 0.f;
    }
    split2(xa, xb, ah, al);
}

// ---------------- kernel 3: register-chained HMMA MLP ----------------------
// CTA = 256 threads = 8 warps; warp w owns rows [blk*128 + 16w, +16).
// Activations never leave registers: C frags of layer l ARE the A frags of
// layer l+1 (m16n8k16 fragment-layout identity).
template <bool ISDP>
__global__ void __launch_bounds__(256, 1) mlp_mma(
    const float* __restrict__ bin, const float* __restrict__ bh,
    const float* __restrict__ Wout, const float* __restrict__ bout) {
    __shared__ __align__(8) float sbias[512];
    __shared__ __align__(8) float swout[128];
    const int tid = threadIdx.x, w = tid >> 5, lane = tid & 31;
    const int q = lane & 3, nr = lane >> 2;

    if (tid < 128) {
        sbias[tid]       = bin[tid];
        sbias[128 + tid] = bh[tid];
        sbias[256 + tid] = bh[128 + tid];
        sbias[384 + tid] = bh[256 + tid];
        swout[tid]       = Wout[tid];
    }
    __syncthreads();

    const int r0 = blockIdx.x * 128 + w * 16 + nr;   // this thread: rows r0, r0+8
    uint32_t a0h, a0l, a1h, a1l;
    build_in<ISDP>(r0, q, a0h, a0l);
    build_in<ISDP>(r0 + 8, q, a1h, a1l);

    const uint2* __restrict__ BH = g_WpH + (ISDP ? 0 : 1) * FRAGS_PER_MLP;
    const uint2* __restrict__ BL = g_WpL + (ISDP ? 0 : 1) * FRAGS_PER_MLP;

    float C[16][4];
    // ---- input layer (1 kstep; k>=8 part of A is zero) ----
#pragma unroll
    for (int j = 0; j < 16; j++) {
        uint2 bhv = __ldg(&BH[j * 32 + lane]);
        uint2 blv = __ldg(&BL[j * 32 + lane]);
        C[j][0] = 0.f; C[j][1] = 0.f; C[j][2] = 0.f; C[j][3] = 0.f;
        mma16816(C[j], a0h, a1h, 0u, 0u, bhv.x, bhv.y);
        mma16816(C[j], a0h, a1h, 0u, 0u, blv.x, blv.y);
        mma16816(C[j], a0l, a1l, 0u, 0u, bhv.x, bhv.y);
    }

    uint32_t Hh0[16], Hh1[16], Hl0[16], Hl1[16];
    // ---- 3 hidden layers ----
#pragma unroll 1
    for (int e = 0; e < 3; e++) {
        // epilogue: bias + tanh + split-pack (C -> H), zero C
#pragma unroll
        for (int j = 0; j < 16; j++) {
            float2 bb = *(const float2*)(sbias + e * 128 + j * 8 + 2 * q);
            float t0 = fast_tanh(C[j][0] + bb.x);
            float t1 = fast_tanh(C[j][1] + bb.y);
            float t2 = fast_tanh(C[j][2] + bb.x);
            float t3 = fast_tanh(C[j][3] + bb.y);
            split2(t0, t1, Hh0[j], Hl0[j]);
            split2(t2, t3, Hh1[j], Hl1[j]);
            C[j][0] = 0.f; C[j][1] = 0.f; C[j][2] = 0.f; C[j][3] = 0.f;
        }
        const uint2* __restrict__ BHe = BH + (1 + e * 8) * 512;
        const uint2* __restrict__ BLe = BL + (1 + e * 8) * 512;
#pragma unroll
        for (int s = 0; s < 8; s++) {
            uint32_t A0h = Hh0[2 * s], A1h = Hh1[2 * s];
            uint32_t A2h = Hh0[2 * s + 1], A3h = Hh1[2 * s + 1];
            uint32_t A0l = Hl0[2 * s], A1l = Hl1[2 * s];
            uint32_t A2l = Hl0[2 * s + 1], A3l = Hl1[2 * s + 1];
#pragma unroll
            for (int j = 0; j < 16; j++) {
                uint2 bhv = __ldg(&BHe[(s * 16 + j) * 32 + lane]);
                uint2 blv = __ldg(&BLe[(s * 16 + j) * 32 + lane]);
                mma16816(C[j], A0h, A1h, A2h, A3h, bhv.x, bhv.y);
                mma16816(C[j], A0h, A1h, A2h, A3h, blv.x, blv.y);
                mma16816(C[j], A0l, A1l, A2l, A3l, bhv.x, bhv.y);
            }
        }
    }

    // ---- final: bias + tanh + dot(Wout) + quad reduce ----
    float s0 = 0.f, s1 = 0.f;
#pragma unroll
    for (int j = 0; j < 16; j++) {
        float2 bb = *(const float2*)(sbias + 384 + j * 8 + 2 * q);
        float2 ww = *(const float2*)(swout + j * 8 + 2 * q);
        s0 = fmaf(fast_tanh(C[j][0] + bb.x), ww.x, s0);
        s0 = fmaf(fast_tanh(C[j][1] + bb.y), ww.y, s0);
        s1 = fmaf(fast_tanh(C[j][2] + bb.x), ww.x, s1);
        s1 = fmaf(fast_tanh(C[j][3] + bb.y), ww.y, s1);
    }
    s0 += __shfl_xor_sync(0xffffffffu, s0, 1);
    s0 += __shfl_xor_sync(0xffffffffu, s0, 2);
    s1 += __shfl_xor_sync(0xffffffffu, s1, 1);
    s1 += __shfl_xor_sync(0xffffffffu, s1, 2);
    if (q == 0) {
        float bo = __ldg(bout);
        float* gout = ISDP ? g_dp : g_ic;
        gout[r0]     = s0 + bo;
        gout[r0 + 8] = s1 + bo;
    }
}

// ---------------- kernel 4: GL quadrature + final scaling ------------------
__global__ void combine_kernel(float* __restrict__ out) {
    int i = blockIdx.x * blockDim.x + threadIdx.x;
    if (i >= NPTS) return;
    const float* f = g_feats + i * 8;
    float a = f[5], inv = f[4];
    const float w0 = (float)(5.0 / 9.0), w1 = (float)(8.0 / 9.0);
    float s = w0 * g_dp[3 * i] + w1 * g_dp[3 * i + 1] + w0 * g_dp[3 * i + 2];
    out[i] = (g_ic[i] + a * s) * inv;
}

// ---------------- host launcher --------------------------------------------
extern "C" void kernel_launch(void* const* d_in, const int* in_sizes, int n_in,
                              void* d_out, int out_size) {
    const float* tx      = (const float*)d_in[0];
    const float* dp_Win  = (const float*)d_in[1];
    const float* dp_bin  = (const float*)d_in[2];
    const float* dp_Wh   = (const float*)d_in[3];
    const float* dp_bh   = (const float*)d_in[4];
    const float* dp_Wout = (const float*)d_in[5];
    const float* dp_bout = (const float*)d_in[6];
    const float* ic_Win  = (const float*)d_in[7];
    const float* ic_bin  = (const float*)d_in[8];
    const float* ic_Wh   = (const float*)d_in[9];
    const float* ic_bh   = (const float*)d_in[10];
    const float* ic_Wout = (const float*)d_in[11];
    const float* ic_bout = (const float*)d_in[12];
    float* out = (float*)d_out;

    prep_kernel<<<NPTS / 256, 256>>>((const float4*)tx);
    wprep_kernel<<<(2 * FRAGS_PER_MLP + 255) / 256, 256>>>(dp_Win, dp_Wh,
                                                           ic_Win, ic_Wh);
    mlp_mma<false><<<NPTS / 128, 256>>>(ic_bin, ic_bh, ic_Wout, ic_bout);
    mlp_mma<true><<<3 * NPTS / 128, 256>>>(dp_bin, dp_bh, dp_Wout, dp_bout);
    combine_kernel<<<NPTS / 256, 256>>>(out);
}

// round 5
// speedup vs baseline: 4.4987x; 1.0270x over previous
#include <cuda_runtime.h>
#include <cuda_bf16.h>
#include <cstdint>

#define NPTS 262144
#define DPBLKS 6144   // 3*NPTS/128
#define ICBLKS 2048   // NPTS/128

// ---------------- scratch (__device__ globals; no allocation allowed) -----
__device__ float g_feats[NPTS * 8];   // [r, ux, uy, uz, inv, a, 0, 0]
__device__ float g_ic[NPTS];
__device__ float g_dp[NPTS * 3];

// Pre-packed B fragments for mma.m16n8k16: one uint4 {h0,h1,l0,l1} per lane
// per frag. Per MLP: 25 ksteps (1 input + 3 layers * 8) x 16 nfrags x 32 lanes.
#define FRAGS_PER_MLP (25 * 16 * 32)   // 12800 uint4
__device__ uint4 g_Wp[2 * FRAGS_PER_MLP];

__constant__ float c_np1[3] = {1.0f - 0.7745966692f, 1.0f, 1.0f + 0.7745966692f};

// ---------------- math helpers --------------------------------------------
__device__ __forceinline__ float fast_tanh(float x) {
    // tanh(x) = 1 - 2/(exp(2x)+1);  ~1e-7 accurate
    float e, r;
    asm("ex2.approx.f32 %0, %1;" : "=f"(e) : "f"(x * 2.8853900817779268f));
    asm("rcp.approx.f32 %0, %1;" : "=f"(r) : "f"(e + 1.0f));
    return fmaf(-2.0f, r, 1.0f);
}
// pack (v0 -> low bf16, v1 -> high bf16); uh = hi parts, ul = residual lo
__device__ __forceinline__ void split2(float v0, float v1, uint32_t& uh, uint32_t& ul) {
    uint32_t u;
    asm("cvt.rn.bf16x2.f32 %0, %1, %2;" : "=r"(u) : "f"(v1), "f"(v0));
    float b0 = __uint_as_float(u << 16);
    float b1 = __uint_as_float(u & 0xffff0000u);
    uh = u;
    asm("cvt.rn.bf16x2.f32 %0, %1, %2;" : "=r"(ul) : "f"(v1 - b1), "f"(v0 - b0));
}

// bf16 HMMA k16: D(16x8) += A(16x16) * B(16x8), fp32 accum
__device__ __forceinline__ void mma16816(float c[4], uint32_t a0, uint32_t a1,
                                         uint32_t a2, uint32_t a3,
                                         uint32_t b0, uint32_t b1) {
    asm volatile(
        "mma.sync.aligned.m16n8k16.row.col.f32.bf16.bf16.f32 "
        "{%0,%1,%2,%3}, {%4,%5,%6,%7}, {%8,%9}, {%0,%1,%2,%3};"
        : "+f"(c[0]), "+f"(c[1]), "+f"(c[2]), "+f"(c[3])
        : "r"(a0), "r"(a1), "r"(a2), "r"(a3), "r"(b0), "r"(b1));
}
// bf16 HMMA k8 (input layer; k>=8 padding eliminated)
__device__ __forceinline__ void mma1688(float c[4], uint32_t a0, uint32_t a1,
                                        uint32_t b0) {
    asm volatile(
        "mma.sync.aligned.m16n8k8.row.col.f32.bf16.bf16.f32 "
        "{%0,%1,%2,%3}, {%4,%5}, {%6}, {%0,%1,%2,%3};"
        : "+f"(c[0]), "+f"(c[1]), "+f"(c[2]), "+f"(c[3])
        : "r"(a0), "r"(a1), "r"(b0));
}

// ---------------- kernel 1: per-point features ----------------------------
__global__ void prep_kernel(const float4* __restrict__ tx) {
    int i = blockIdx.x * blockDim.x + threadIdx.x;
    if (i >= NPTS) return;
    float4 v = tx[i];
    float r = sqrtf(v.y * v.y + v.z * v.z + v.w * v.w);
    float rs = fmaxf(r, 1e-8f);
    float inv = 1.0f / (1.0f + r);
    float a = v.x * 0.5f;   // T0 = 0; CLIP = 1 -> min(r, max r) == r
    float* o = g_feats + i * 8;
    ((float4*)o)[0] = make_float4(r, v.y / rs, v.z / rs, v.w / rs);
    ((float4*)o)[1] = make_float4(inv, a, 0.f, 0.f);
}

// ---------------- kernel 2: pack weights into B-fragment layout ------------
// B frag (k16n8, col-major): b0 = (k = 2q, 2q+1; n = 8j + lane/4),
//                            b1 = (k = 8+2q, 8+2q+1; same n)
__global__ void wprep_kernel(const float* __restrict__ dp_Win,
                             const float* __restrict__ dp_Wh,
                             const float* __restrict__ ic_Win,
                             const float* __restrict__ ic_Wh) {
    int t = blockIdx.x * blockDim.x + threadIdx.x;
    if (t >= 2 * FRAGS_PER_MLP) return;
    int lane = t & 31;
    int g = t >> 5;                // 0..799
    int m = g / 400;               // 0 = dp, 1 = ic
    int gg = g - m * 400;
    int ks = gg >> 4;              // 0 = input layer, 1..24 = hidden
    int j = gg & 15;
    const float* Win = m ? ic_Win : dp_Win;
    const float* Wh  = m ? ic_Wh  : dp_Wh;
    int din = m ? 5 : 6;
    int q = lane & 3;
    int n = j * 8 + (lane >> 2);
    float w00, w01, w10, w11;
    if (ks == 0) {
        int k0 = 2 * q;
        w00 = (k0     < din) ? Win[k0 * 128 + n]       : 0.f;
        w01 = (k0 + 1 < din) ? Win[(k0 + 1) * 128 + n] : 0.f;
        w10 = 0.f; w11 = 0.f;
    } else {
        int l = (ks - 1) >> 3, s = (ks - 1) & 7;
        int kb = 16 * s + 2 * q;
        const float* W = Wh + l * 16384;
        w00 = W[kb * 128 + n];       w01 = W[(kb + 1) * 128 + n];
        w10 = W[(kb + 8) * 128 + n]; w11 = W[(kb + 9) * 128 + n];
    }
    uint32_t h0, l0, h1, l1;
    split2(w00, w01, h0, l0);
    split2(w10, w11, h1, l1);
    g_Wp[t] = make_uint4(h0, h1, l0, l1);
}

// ---------------- input A-fragment builder --------------------------------
__device__ __forceinline__ void build_in(bool isdp, int grow, int q,
                                         uint32_t& ah, uint32_t& al) {
    float xa, xb;
    if (isdp) {
        int p = grow / 3, nd = grow - 3 * p;
        float4 f0 = *(const float4*)(g_feats + p * 8);       // r ux uy uz
        float2 f1 = *(const float2*)(g_feats + p * 8 + 4);   // inv a
        float tt = f1.y * c_np1[nd];
        // x = [t, r, ux, uy, uz, inv, 0, 0]
        xa = (q == 0) ? tt   : (q == 1) ? f0.y : (q == 2) ? f0.w : 0.f;
        xb = (q == 0) ? f0.x : (q == 1) ? f0.z : (q == 2) ? f1.x : 0.f;
    } else {
        float4 f0 = *(const float4*)(g_feats + grow * 8);
        float2 f1 = *(const float2*)(g_feats + grow * 8 + 4);
        // x = [r, ux, uy, uz, inv, 0, 0, 0]
        xa = (q == 0) ? f0.x : (q == 1) ? f0.z : (q == 2) ? f1.x : 0.f;
        xb = (q == 0) ? f0.y : (q == 1) ? f0.w : 0.f;
    }
    split2(xa, xb, ah, al);
}

// ---------------- kernel 3: register-chained HMMA MLP (merged IC+DP) -------
// 256 threads = 8 warps; warp w owns 16 rows. Activations never leave
// registers: C frags of layer l ARE the A frags of layer l+1.
__global__ void __launch_bounds__(256, 1) mlp_mma(
    const float* __restrict__ dp_bin, const float* __restrict__ dp_bh,
    const float* __restrict__ dp_Wout, const float* __restrict__ dp_bout,
    const float* __restrict__ ic_bin, const float* __restrict__ ic_bh,
    const float* __restrict__ ic_Wout, const float* __restrict__ ic_bout) {
    __shared__ __align__(8) float sbias[512];
    __shared__ __align__(8) float swout[128];
    const bool isdp = blockIdx.x < DPBLKS;
    const int rowblk = isdp ? blockIdx.x : (blockIdx.x - DPBLKS);
    const float* bin  = isdp ? dp_bin  : ic_bin;
    const float* bh   = isdp ? dp_bh   : ic_bh;
    const float* Wout = isdp ? dp_Wout : ic_Wout;
    const float* bout = isdp ? dp_bout : ic_bout;

    const int tid = threadIdx.x, w = tid >> 5, lane = tid & 31;
    const int q = lane & 3, nr = lane >> 2;

    if (tid < 128) {
        sbias[tid]       = bin[tid];
        sbias[128 + tid] = bh[tid];
        sbias[256 + tid] = bh[128 + tid];
        sbias[384 + tid] = bh[256 + tid];
        swout[tid]       = Wout[tid];
    }
    __syncthreads();

    const int r0 = rowblk * 128 + w * 16 + nr;   // this thread: rows r0, r0+8
    uint32_t a0h, a0l, a1h, a1l;
    build_in(isdp, r0, q, a0h, a0l);
    build_in(isdp, r0 + 8, q, a1h, a1l);

    const uint4* __restrict__ Bp = g_Wp + (isdp ? 0 : 1) * FRAGS_PER_MLP;

    float C[16][4];
    // ---- input layer: k8 mma (real k <= 6), prefetch distance 1 ----
    {
        uint4 b = __ldg(&Bp[lane]);
#pragma unroll
        for (int j = 0; j < 16; j++) {
            int jn = (j + 1 < 16) ? j + 1 : 15;
            uint4 bn = __ldg(&Bp[jn * 32 + lane]);
            C[j][0] = 0.f; C[j][1] = 0.f; C[j][2] = 0.f; C[j][3] = 0.f;
            mma1688(C[j], a0h, a1h, b.x);
            mma1688(C[j], a0h, a1h, b.z);
            mma1688(C[j], a0l, a1l, b.x);
            b = bn;
        }
    }

    uint32_t Hh0[16], Hh1[16], Hl0[16], Hl1[16];
    // ---- 3 hidden layers ----
#pragma unroll 1
    for (int e = 0; e < 3; e++) {
        // epilogue: bias + tanh + split-pack (C -> H), zero C
#pragma unroll
        for (int j = 0; j < 16; j++) {
            float2 bb = *(const float2*)(sbias + e * 128 + j * 8 + 2 * q);
            float t0 = fast_tanh(C[j][0] + bb.x);
            float t1 = fast_tanh(C[j][1] + bb.y);
            float t2 = fast_tanh(C[j][2] + bb.x);
            float t3 = fast_tanh(C[j][3] + bb.y);
            split2(t0, t1, Hh0[j], Hl0[j]);
            split2(t2, t3, Hh1[j], Hl1[j]);
            C[j][0] = 0.f; C[j][1] = 0.f; C[j][2] = 0.f; C[j][3] = 0.f;
        }
        const uint4* __restrict__ BL = Bp + (1 + e * 8) * 512;
        uint4 b = __ldg(&BL[lane]);
#pragma unroll
        for (int s = 0; s < 8; s++) {
            uint32_t A0h = Hh0[2 * s], A1h = Hh1[2 * s];
            uint32_t A2h = Hh0[2 * s + 1], A3h = Hh1[2 * s + 1];
            uint32_t A0l = Hl0[2 * s], A1l = Hl1[2 * s];
            uint32_t A2l = Hl0[2 * s + 1], A3l = Hl1[2 * s + 1];
#pragma unroll
            for (int j = 0; j < 16; j++) {
                int f = s * 16 + j;
                int fn = (f + 1 < 128) ? f + 1 : 127;
                uint4 bn = __ldg(&BL[fn * 32 + lane]);
                mma16816(C[j], A0h, A1h, A2h, A3h, b.x, b.y);
                mma16816(C[j], A0h, A1h, A2h, A3h, b.z, b.w);
                mma16816(C[j], A0l, A1l, A2l, A3l, b.x, b.y);
                b = bn;
            }
        }
    }

    // ---- final: bias + tanh + dot(Wout) + quad reduce ----
    float s0 = 0.f, s1 = 0.f;
#pragma unroll
    for (int j = 0; j < 16; j++) {
        float2 bb = *(const float2*)(sbias + 384 + j * 8 + 2 * q);
        float2 ww = *(const float2*)(swout + j * 8 + 2 * q);
        s0 = fmaf(fast_tanh(C[j][0] + bb.x), ww.x, s0);
        s0 = fmaf(fast_tanh(C[j][1] + bb.y), ww.y, s0);
        s1 = fmaf(fast_tanh(C[j][2] + bb.x), ww.x, s1);
        s1 = fmaf(fast_tanh(C[j][3] + bb.y), ww.y, s1);
    }
    s0 += __shfl_xor_sync(0xffffffffu, s0, 1);
    s0 += __shfl_xor_sync(0xffffffffu, s0, 2);
    s1 += __shfl_xor_sync(0xffffffffu, s1, 1);
    s1 += __shfl_xor_sync(0xffffffffu, s1, 2);
    if (q == 0) {
        float bo = __ldg(bout);
        float* gout = isdp ? g_dp : g_ic;
        gout[r0]     = s0 + bo;
        gout[r0 + 8] = s1 + bo;
    }
}

// ---------------- kernel 4: GL quadrature + final scaling ------------------
__global__ void combine_kernel(float* __restrict__ out) {
    int i = blockIdx.x * blockDim.x + threadIdx.x;
    if (i >= NPTS) return;
    const float* f = g_feats + i * 8;
    float a = f[5], inv = f[4];
    const float w0 = (float)(5.0 / 9.0), w1 = (float)(8.0 / 9.0);
    float s = w0 * g_dp[3 * i] + w1 * g_dp[3 * i + 1] + w0 * g_dp[3 * i + 2];
    out[i] = (g_ic[i] + a * s) * inv;
}

// ---------------- host launcher --------------------------------------------
extern "C" void kernel_launch(void* const* d_in, const int* in_sizes, int n_in,
                              void* d_out, int out_size) {
    const float* tx      = (const float*)d_in[0];
    const float* dp_Win  = (const float*)d_in[1];
    const float* dp_bin  = (const float*)d_in[2];
    const float* dp_Wh   = (const float*)d_in[3];
    const float* dp_bh   = (const float*)d_in[4];
    const float* dp_Wout = (const float*)d_in[5];
    const float* dp_bout = (const float*)d_in[6];
    const float* ic_Win  = (const float*)d_in[7];
    const float* ic_bin  = (const float*)d_in[8];
    const float* ic_Wh   = (const float*)d_in[9];
    const float* ic_bh   = (const float*)d_in[10];
    const float* ic_Wout = (const float*)d_in[11];
    const float* ic_bout = (const float*)d_in[12];
    float* out = (float*)d_out;

    prep_kernel<<<NPTS / 256, 256>>>((const float4*)tx);
    wprep_kernel<<<(2 * FRAGS_PER_MLP + 255) / 256, 256>>>(dp_Win, dp_Wh,
                                                           ic_Win, ic_Wh);
    mlp_mma<<<DPBLKS + ICBLKS, 256>>>(dp_bin, dp_bh, dp_Wout, dp_bout,
                                      ic_bin, ic_bh, ic_Wout, ic_bout);
    combine_kernel<<<NPTS / 256, 256>>>(out);
}

// round 6
// speedup vs baseline: 4.5647x; 1.0147x over previous
#include <cuda_runtime.h>
#include <cuda_bf16.h>
#include <cstdint>

#define NPTS 262144
#define DPBLKS 6144   // 3*NPTS/128
#define ICBLKS 2048   // NPTS/128

// ---------------- scratch (__device__ globals; no allocation allowed) -----
__device__ float g_feats[NPTS * 8];   // [r, ux, uy, uz, inv, a, 0, 0]
__device__ float g_ic[NPTS];
__device__ float g_dp[NPTS * 3];

// Pre-packed B fragments for mma.m16n8k16: one uint4 {h0,h1,l0,l1} per lane
// per frag. Per MLP: 25 ksteps (1 input + 3 layers * 8) x 16 nfrags x 32 lanes.
#define FRAGS_PER_MLP (25 * 16 * 32)   // 12800 uint4
__device__ uint4 g_Wp[2 * FRAGS_PER_MLP];

__constant__ float c_np1[3] = {1.0f - 0.7745966692f, 1.0f, 1.0f + 0.7745966692f};

// ---------------- math helpers --------------------------------------------
__device__ __forceinline__ float fast_tanh(float x) {
    // tanh(x) = 1 - 2/(exp(2x)+1);  ~1e-7 accurate
    float e, r;
    asm("ex2.approx.f32 %0, %1;" : "=f"(e) : "f"(x * 2.8853900817779268f));
    asm("rcp.approx.f32 %0, %1;" : "=f"(r) : "f"(e + 1.0f));
    return fmaf(-2.0f, r, 1.0f);
}
// pack (v0 -> low bf16, v1 -> high bf16); uh = hi parts, ul = residual lo
__device__ __forceinline__ void split2(float v0, float v1, uint32_t& uh, uint32_t& ul) {
    uint32_t u;
    asm("cvt.rn.bf16x2.f32 %0, %1, %2;" : "=r"(u) : "f"(v1), "f"(v0));
    float b0 = __uint_as_float(u << 16);
    float b1 = __uint_as_float(u & 0xffff0000u);
    uh = u;
    asm("cvt.rn.bf16x2.f32 %0, %1, %2;" : "=r"(ul) : "f"(v1 - b1), "f"(v0 - b0));
}

// bf16 HMMA k16: D(16x8) += A(16x16) * B(16x8), fp32 accum
__device__ __forceinline__ void mma16816(float c[4], uint32_t a0, uint32_t a1,
                                         uint32_t a2, uint32_t a3,
                                         uint32_t b0, uint32_t b1) {
    asm volatile(
        "mma.sync.aligned.m16n8k16.row.col.f32.bf16.bf16.f32 "
        "{%0,%1,%2,%3}, {%4,%5,%6,%7}, {%8,%9}, {%0,%1,%2,%3};"
        : "+f"(c[0]), "+f"(c[1]), "+f"(c[2]), "+f"(c[3])
        : "r"(a0), "r"(a1), "r"(a2), "r"(a3), "r"(b0), "r"(b1));
}
// bf16 HMMA k8 (input layer; k>=8 padding eliminated)
__device__ __forceinline__ void mma1688(float c[4], uint32_t a0, uint32_t a1,
                                        uint32_t b0) {
    asm volatile(
        "mma.sync.aligned.m16n8k8.row.col.f32.bf16.bf16.f32 "
        "{%0,%1,%2,%3}, {%4,%5}, {%6}, {%0,%1,%2,%3};"
        : "+f"(c[0]), "+f"(c[1]), "+f"(c[2]), "+f"(c[3])
        : "r"(a0), "r"(a1), "r"(b0));
}

// ---------------- kernel 1: per-point features ----------------------------
__global__ void prep_kernel(const float4* __restrict__ tx) {
    int i = blockIdx.x * blockDim.x + threadIdx.x;
    if (i >= NPTS) return;
    float4 v = tx[i];
    float r = sqrtf(v.y * v.y + v.z * v.z + v.w * v.w);
    float rs = fmaxf(r, 1e-8f);
    float inv = 1.0f / (1.0f + r);
    float a = v.x * 0.5f;   // T0 = 0; CLIP = 1 -> min(r, max r) == r
    float* o = g_feats + i * 8;
    ((float4*)o)[0] = make_float4(r, v.y / rs, v.z / rs, v.w / rs);
    ((float4*)o)[1] = make_float4(inv, a, 0.f, 0.f);
}

// ---------------- kernel 2: pack weights into B-fragment layout ------------
__global__ void wprep_kernel(const float* __restrict__ dp_Win,
                             const float* __restrict__ dp_Wh,
                             const float* __restrict__ ic_Win,
                             const float* __restrict__ ic_Wh) {
    int t = blockIdx.x * blockDim.x + threadIdx.x;
    if (t >= 2 * FRAGS_PER_MLP) return;
    int lane = t & 31;
    int g = t >> 5;                // 0..799
    int m = g / 400;               // 0 = dp, 1 = ic
    int gg = g - m * 400;
    int ks = gg >> 4;              // 0 = input layer, 1..24 = hidden
    int j = gg & 15;
    const float* Win = m ? ic_Win : dp_Win;
    const float* Wh  = m ? ic_Wh  : dp_Wh;
    int din = m ? 5 : 6;
    int q = lane & 3;
    int n = j * 8 + (lane >> 2);
    float w00, w01, w10, w11;
    if (ks == 0) {
        int k0 = 2 * q;
        w00 = (k0     < din) ? Win[k0 * 128 + n]       : 0.f;
        w01 = (k0 + 1 < din) ? Win[(k0 + 1) * 128 + n] : 0.f;
        w10 = 0.f; w11 = 0.f;
    } else {
        int l = (ks - 1) >> 3, s = (ks - 1) & 7;
        int kb = 16 * s + 2 * q;
        const float* W = Wh + l * 16384;
        w00 = W[kb * 128 + n];       w01 = W[(kb + 1) * 128 + n];
        w10 = W[(kb + 8) * 128 + n]; w11 = W[(kb + 9) * 128 + n];
    }
    uint32_t h0, l0, h1, l1;
    split2(w00, w01, h0, l0);
    split2(w10, w11, h1, l1);
    g_Wp[t] = make_uint4(h0, h1, l0, l1);
}

// ---------------- input A-fragment builder --------------------------------
__device__ __forceinline__ void build_in(bool isdp, int grow, int q,
                                         uint32_t& ah, uint32_t& al) {
    float xa, xb;
    if (isdp) {
        int p = grow / 3, nd = grow - 3 * p;
        float4 f0 = *(const float4*)(g_feats + p * 8);       // r ux uy uz
        float2 f1 = *(const float2*)(g_feats + p * 8 + 4);   // inv a
        float tt = f1.y * c_np1[nd];
        // x = [t, r, ux, uy, uz, inv, 0, 0]
        xa = (q == 0) ? tt   : (q == 1) ? f0.y : (q == 2) ? f0.w : 0.f;
        xb = (q == 0) ? f0.x : (q == 1) ? f0.z : (q == 2) ? f1.x : 0.f;
    } else {
        float4 f0 = *(const float4*)(g_feats + grow * 8);
        float2 f1 = *(const float2*)(g_feats + grow * 8 + 4);
        // x = [r, ux, uy, uz, inv, 0, 0, 0]
        xa = (q == 0) ? f0.x : (q == 1) ? f0.z : (q == 2) ? f1.x : 0.f;
        xb = (q == 0) ? f0.y : (q == 1) ? f0.w : 0.f;
    }
    split2(xa, xb, ah, al);
}

// ---------------- kernel 3: register-chained HMMA MLP (merged IC+DP) -------
// 256 threads = 8 warps; warp w owns 16 rows. Activations never leave
// registers: C frags of layer l ARE the A frags of layer l+1.
// Inner loops are product-major over groups of 4 j's so consecutive HMMAs
// never target the same accumulator (RAW distance 4).
__global__ void __launch_bounds__(256, 1) mlp_mma(
    const float* __restrict__ dp_bin, const float* __restrict__ dp_bh,
    const float* __restrict__ dp_Wout, const float* __restrict__ dp_bout,
    const float* __restrict__ ic_bin, const float* __restrict__ ic_bh,
    const float* __restrict__ ic_Wout, const float* __restrict__ ic_bout) {
    __shared__ __align__(8) float sbias[512];
    __shared__ __align__(8) float swout[128];
    const bool isdp = blockIdx.x < DPBLKS;
    const int rowblk = isdp ? blockIdx.x : (blockIdx.x - DPBLKS);
    const float* bin  = isdp ? dp_bin  : ic_bin;
    const float* bh   = isdp ? dp_bh   : ic_bh;
    const float* Wout = isdp ? dp_Wout : ic_Wout;
    const float* bout = isdp ? dp_bout : ic_bout;

    const int tid = threadIdx.x, w = tid >> 5, lane = tid & 31;
    const int q = lane & 3, nr = lane >> 2;

    if (tid < 128) {
        sbias[tid]       = bin[tid];
        sbias[128 + tid] = bh[tid];
        sbias[256 + tid] = bh[128 + tid];
        sbias[384 + tid] = bh[256 + tid];
        swout[tid]       = Wout[tid];
    }
    __syncthreads();

    const int r0 = rowblk * 128 + w * 16 + nr;   // this thread: rows r0, r0+8
    uint32_t a0h, a0l, a1h, a1l;
    build_in(isdp, r0, q, a0h, a0l);
    build_in(isdp, r0 + 8, q, a1h, a1l);

    const uint4* __restrict__ Bp = g_Wp + (isdp ? 0 : 1) * FRAGS_PER_MLP;

    float C[16][4];
#pragma unroll
    for (int j = 0; j < 16; j++) {
        C[j][0] = 0.f; C[j][1] = 0.f; C[j][2] = 0.f; C[j][3] = 0.f;
    }

    // ---- input layer: k8 mma, groups of 4, product-major ----
#pragma unroll
    for (int jg = 0; jg < 4; jg++) {
        uint4 b0 = __ldg(&Bp[(jg * 4 + 0) * 32 + lane]);
        uint4 b1 = __ldg(&Bp[(jg * 4 + 1) * 32 + lane]);
        uint4 b2 = __ldg(&Bp[(jg * 4 + 2) * 32 + lane]);
        uint4 b3 = __ldg(&Bp[(jg * 4 + 3) * 32 + lane]);
        mma1688(C[jg * 4 + 0], a0h, a1h, b0.x);
        mma1688(C[jg * 4 + 1], a0h, a1h, b1.x);
        mma1688(C[jg * 4 + 2], a0h, a1h, b2.x);
        mma1688(C[jg * 4 + 3], a0h, a1h, b3.x);
        mma1688(C[jg * 4 + 0], a0h, a1h, b0.z);
        mma1688(C[jg * 4 + 1], a0h, a1h, b1.z);
        mma1688(C[jg * 4 + 2], a0h, a1h, b2.z);
        mma1688(C[jg * 4 + 3], a0h, a1h, b3.z);
        mma1688(C[jg * 4 + 0], a0l, a1l, b0.x);
        mma1688(C[jg * 4 + 1], a0l, a1l, b1.x);
        mma1688(C[jg * 4 + 2], a0l, a1l, b2.x);
        mma1688(C[jg * 4 + 3], a0l, a1l, b3.x);
    }

    uint32_t Hh0[16], Hh1[16], Hl0[16], Hl1[16];
    // ---- 3 hidden layers ----
#pragma unroll 1
    for (int e = 0; e < 3; e++) {
        // epilogue: bias + tanh + split-pack (C -> H), zero C
#pragma unroll
        for (int j = 0; j < 16; j++) {
            float2 bb = *(const float2*)(sbias + e * 128 + j * 8 + 2 * q);
            float t0 = fast_tanh(C[j][0] + bb.x);
            float t1 = fast_tanh(C[j][1] + bb.y);
            float t2 = fast_tanh(C[j][2] + bb.x);
            float t3 = fast_tanh(C[j][3] + bb.y);
            split2(t0, t1, Hh0[j], Hl0[j]);
            split2(t2, t3, Hh1[j], Hl1[j]);
            C[j][0] = 0.f; C[j][1] = 0.f; C[j][2] = 0.f; C[j][3] = 0.f;
        }
        const uint4* __restrict__ BL = Bp + (1 + e * 8) * 512;
#pragma unroll
        for (int s = 0; s < 8; s++) {
            const uint32_t A0h = Hh0[2 * s], A1h = Hh1[2 * s];
            const uint32_t A2h = Hh0[2 * s + 1], A3h = Hh1[2 * s + 1];
            const uint32_t A0l = Hl0[2 * s], A1l = Hl1[2 * s];
            const uint32_t A2l = Hl0[2 * s + 1], A3l = Hl1[2 * s + 1];
#pragma unroll
            for (int jg = 0; jg < 4; jg++) {
                const uint4* bp = &BL[(s * 16 + jg * 4) * 32 + lane];
                uint4 b0 = __ldg(bp);
                uint4 b1 = __ldg(bp + 32);
                uint4 b2 = __ldg(bp + 64);
                uint4 b3 = __ldg(bp + 96);
                float* c0 = C[jg * 4 + 0];
                float* c1 = C[jg * 4 + 1];
                float* c2 = C[jg * 4 + 2];
                float* c3 = C[jg * 4 + 3];
                mma16816(c0, A0h, A1h, A2h, A3h, b0.x, b0.y);
                mma16816(c1, A0h, A1h, A2h, A3h, b1.x, b1.y);
                mma16816(c2, A0h, A1h, A2h, A3h, b2.x, b2.y);
                mma16816(c3, A0h, A1h, A2h, A3h, b3.x, b3.y);
                mma16816(c0, A0h, A1h, A2h, A3h, b0.z, b0.w);
                mma16816(c1, A0h, A1h, A2h, A3h, b1.z, b1.w);
                mma16816(c2, A0h, A1h, A2h, A3h, b2.z, b2.w);
                mma16816(c3, A0h, A1h, A2h, A3h, b3.z, b3.w);
                mma16816(c0, A0l, A1l, A2l, A3l, b0.x, b0.y);
                mma16816(c1, A0l, A1l, A2l, A3l, b1.x, b1.y);
                mma16816(c2, A0l, A1l, A2l, A3l, b2.x, b2.y);
                mma16816(c3, A0l, A1l, A2l, A3l, b3.x, b3.y);
            }
        }
    }

    // ---- final: bias + tanh + dot(Wout) + quad reduce ----
    float s0 = 0.f, s1 = 0.f;
#pragma unroll
    for (int j = 0; j < 16; j++) {
        float2 bb = *(const float2*)(sbias + 384 + j * 8 + 2 * q);
        float2 ww = *(const float2*)(swout + j * 8 + 2 * q);
        s0 = fmaf(fast_tanh(C[j][0] + bb.x), ww.x, s0);
        s0 = fmaf(fast_tanh(C[j][1] + bb.y), ww.y, s0);
        s1 = fmaf(fast_tanh(C[j][2] + bb.x), ww.x, s1);
        s1 = fmaf(fast_tanh(C[j][3] + bb.y), ww.y, s1);
    }
    s0 += __shfl_xor_sync(0xffffffffu, s0, 1);
    s0 += __shfl_xor_sync(0xffffffffu, s0, 2);
    s1 += __shfl_xor_sync(0xffffffffu, s1, 1);
    s1 += __shfl_xor_sync(0xffffffffu, s1, 2);
    if (q == 0) {
        float bo = __ldg(bout);
        float* gout = isdp ? g_dp : g_ic;
        gout[r0]     = s0 + bo;
        gout[r0 + 8] = s1 + bo;
    }
}

// ---------------- kernel 4: GL quadrature + final scaling ------------------
__global__ void combine_kernel(float* __restrict__ out) {
    int i = blockIdx.x * blockDim.x + threadIdx.x;
    if (i >= NPTS) return;
    const float* f = g_feats + i * 8;
    float a = f[5], inv = f[4];
    const float w0 = (float)(5.0 / 9.0), w1 = (float)(8.0 / 9.0);
    float s = w0 * g_dp[3 * i] + w1 * g_dp[3 * i + 1] + w0 * g_dp[3 * i + 2];
    out[i] = (g_ic[i] + a * s) * inv;
}

// ---------------- host launcher --------------------------------------------
extern "C" void kernel_launch(void* const* d_in, const int* in_sizes, int n_in,
                              void* d_out, int out_size) {
    const float* tx      = (const float*)d_in[0];
    const float* dp_Win  = (const float*)d_in[1];
    const float* dp_bin  = (const float*)d_in[2];
    const float* dp_Wh   = (const float*)d_in[3];
    const float* dp_bh   = (const float*)d_in[4];
    const float* dp_Wout = (const float*)d_in[5];
    const float* dp_bout = (const float*)d_in[6];
    const float* ic_Win  = (const float*)d_in[7];
    const float* ic_bin  = (const float*)d_in[8];
    const float* ic_Wh   = (const float*)d_in[9];
    const float* ic_bh   = (const float*)d_in[10];
    const float* ic_Wout = (const float*)d_in[11];
    const float* ic_bout = (const float*)d_in[12];
    float* out = (float*)d_out;

    prep_kernel<<<NPTS / 256, 256>>>((const float4*)tx);
    wprep_kernel<<<(2 * FRAGS_PER_MLP + 255) / 256, 256>>>(dp_Win, dp_Wh,
                                                           ic_Win, ic_Wh);
    mlp_mma<<<DPBLKS + ICBLKS, 256>>>(dp_bin, dp_bh, dp_Wout, dp_bout,
                                      ic_bin, ic_bh, ic_Wout, ic_bout);
    combine_kernel<<<NPTS / 256, 256>>>(out);
}